// round 9
// baseline (speedup 1.0000x reference)
#include <cuda_runtime.h>

#define NPHI 128
#define DEG  127

typedef unsigned long long u64;

// Coefficients C_j of a(w) = w^{-127} * sum_j C_j * (w^2)^j  (complex, 128 entries)
__device__ float2 g_coefA[NPHI];
// Lane-duplicated interleaved (CR, CI) u64 pairs, staged for the constant bank
__device__ u64 g_coefDup[2 * NPHI];
// Constant-bank copy: warp-uniform reads -> LDCU -> uniform registers ->
// FFMA2 with UR addend reads uniform RF, cutting vector-RF bank rt 3 -> 2.
__constant__ u64 c_coef[2 * NPHI];

// ---------------------------------------------------------------------------
// Kernel 1: build the 128 complex coefficients from the phis (one block).
// Pointwise-unitary recurrence => coefficient l2-norm preserved => stable fp32.
// ---------------------------------------------------------------------------
__global__ void qsp_coeff_kernel(const float* __restrict__ phis) {
    __shared__ float er[NPHI], ei[NPHI];
    __shared__ float Ar[2][NPHI + 1], Ai[2][NPHI + 1];
    __shared__ float Br[2][NPHI + 1], Bi[2][NPHI + 1];
    int j = threadIdx.x;  // 0..127

    float s, c;
    sincosf(phis[j], &s, &c);
    er[j] = c; ei[j] = s;

    Ar[0][j + 1] = 0.f; Ai[0][j + 1] = 0.f;
    Br[0][j + 1] = 0.f; Bi[0][j + 1] = 0.f;
    Ar[1][j + 1] = 0.f; Ai[1][j + 1] = 0.f;
    Br[1][j + 1] = 0.f; Bi[1][j + 1] = 0.f;
    if (j == 0) {
        Ar[0][0] = Ai[0][0] = Br[0][0] = Bi[0][0] = 0.f;
        Ar[1][0] = Ai[1][0] = Br[1][0] = Bi[1][0] = 0.f;
    }
    __syncthreads();
    if (j == 0) { Ar[0][1] = er[0]; Ai[0][1] = ei[0]; }  // A_0 = e^{i phi_0}
    __syncthreads();

    int p = 0;
    for (int k = 1; k <= DEG; k++) {
        int q = p ^ 1;
        float am1r = Ar[p][j],     am1i = Ai[p][j];
        float a0r  = Ar[p][j + 1], a0i  = Ai[p][j + 1];
        float bm1r = Br[p][j],     bm1i = Bi[p][j];
        float b0r  = Br[p][j + 1], b0i  = Bi[p][j + 1];

        float tAr = 0.5f * (am1r + a0r + bm1r - b0r);
        float tAi = 0.5f * (am1i + a0i + bm1i - b0i);
        float tBr = 0.5f * (am1r - a0r + bm1r + b0r);
        float tBi = 0.5f * (am1i - a0i + bm1i + b0i);

        float ekr = er[k], eki = ei[k];
        Ar[q][j + 1] = ekr * tAr - eki * tAi;   // e_k * tA
        Ai[q][j + 1] = ekr * tAi + eki * tAr;
        Br[q][j + 1] = ekr * tBr + eki * tBi;   // conj(e_k) * tB
        Bi[q][j + 1] = ekr * tBi - eki * tBr;

        p = q;
        __syncthreads();
    }
    float cr = Ar[p][j + 1], ci = Ai[p][j + 1];
    g_coefA[j] = make_float2(cr, ci);
    // lane-duplicated packed layout for the main kernel's constant bank
    u64 pr, pi;
    asm("mov.b64 %0,{%1,%1};" : "=l"(pr) : "f"(cr));
    asm("mov.b64 %0,{%1,%1};" : "=l"(pi) : "f"(ci));
    g_coefDup[2 * j]     = pr;
    g_coefDup[2 * j + 1] = pi;
}

// ---------------------------------------------------------------------------
// Packed f32x2 helpers
// ---------------------------------------------------------------------------
__device__ __forceinline__ u64 pk2(float lo, float hi) {
    u64 r; asm("mov.b64 %0,{%1,%2};" : "=l"(r) : "f"(lo), "f"(hi)); return r;
}
__device__ __forceinline__ void upk2(u64 v, float& lo, float& hi) {
    asm("mov.b64 {%0,%1},%2;" : "=f"(lo), "=f"(hi) : "l"(v));
}
__device__ __forceinline__ u64 ffma2(u64 a, u64 b, u64 c) {
    u64 d; asm("fma.rn.f32x2 %0,%1,%2,%3;" : "=l"(d) : "l"(a), "l"(b), "l"(c)); return d;
}
__device__ __forceinline__ u64 fmul2(u64 a, u64 b) {
    u64 d; asm("mul.rn.f32x2 %0,%1,%2;" : "=l"(d) : "l"(a), "l"(b)); return d;
}
__device__ __forceinline__ u64 fsub2(u64 a, u64 b) {
    u64 d; asm("sub.rn.f32x2 %0,%1,%2;" : "=l"(d) : "l"(a), "l"(b)); return d;
}
__device__ __forceinline__ u64 neg2(u64 a) {
    return a ^ 0x8000000080000000ULL;  // flip both fp32 sign bits
}

// ---------------------------------------------------------------------------
// Kernel 2: 4 thetas/thread = two packed (f32x2) Goertzel chains.
//   P(z) = sum_j C_j z^j,  z = e^{2i theta}:
//     b_k = (y*b_{k+1} + C_k) - b_{k+2},  y = 2 Re(z)   (C_k from const bank:
//     FFMA2 addend is a uniform register -> 2 distinct vector pairs -> rt2)
//     P   = b_0 - conj(z)*b_1
//   result = P * e^{-127 i theta}  (direct __sincosf(127*theta))
// ---------------------------------------------------------------------------
__global__ void __launch_bounds__(256) qsp_main_kernel(const float* __restrict__ th,
                                                       float* __restrict__ out, int B) {
    int t = threadIdx.x;
    int base = (blockIdx.x * blockDim.x + t) * 4;
    if (base >= B) return;

    float4 T = *(const float4*)(th + base);

    float zr0, zi0, zr1, zi1, zr2, zi2, zr3, zi3;   // z = e^{2i theta}
    float cm0, sm0, cm1, sm1, cm2, sm2, cm3, sm3;   // e^{i*127 theta}
    __sincosf(2.f * T.x, &zi0, &zr0);
    __sincosf(2.f * T.y, &zi1, &zr1);
    __sincosf(2.f * T.z, &zi2, &zr2);
    __sincosf(2.f * T.w, &zi3, &zr3);
    __sincosf(127.f * T.x, &sm0, &cm0);
    __sincosf(127.f * T.y, &sm1, &cm1);
    __sincosf(127.f * T.z, &sm2, &cm2);
    __sincosf(127.f * T.w, &sm3, &cm3);

    u64 ZRa = pk2(zr0, zr1), ZIa = pk2(zi0, zi1);
    u64 ZRb = pk2(zr2, zr3), ZIb = pk2(zi2, zi3);
    u64 Ya  = pk2(2.f * zr0, 2.f * zr1);           // 2*Re(z)
    u64 Yb  = pk2(2.f * zr2, 2.f * zr3);
    u64 CMa = pk2(cm0, cm1), SMa = pk2(sm0, sm1);
    u64 CMb = pk2(cm2, cm3), SMb = pk2(sm2, sm3);

    // Goertzel init: b_127 = C_127, b_128 = 0
    u64 B1ra = c_coef[2 * DEG], B1ia = c_coef[2 * DEG + 1];
    u64 B1rb = B1ra, B1ib = B1ia;
    u64 B2ra = 0, B2ia = 0, B2rb = 0, B2ib = 0;

#pragma unroll 8
    for (int k = DEG - 1; k >= 0; k--) {
        u64 CR = c_coef[2 * k];
        u64 CI = c_coef[2 * k + 1];
        // chain a
        u64 nra = fsub2(ffma2(Ya, B1ra, CR), B2ra);
        u64 nia = fsub2(ffma2(Ya, B1ia, CI), B2ia);
        B2ra = B1ra; B2ia = B1ia; B1ra = nra; B1ia = nia;
        // chain b
        u64 nrb = fsub2(ffma2(Yb, B1rb, CR), B2rb);
        u64 nib = fsub2(ffma2(Yb, B1ib, CI), B2ib);
        B2rb = B1rb; B2ib = B1ib; B1rb = nrb; B1ib = nib;
    }
    // B1 = b_0, B2 = b_1.  P = b_0 - conj(z)*b_1
    u64 qra = ffma2(ZRa, B2ra, fmul2(ZIa, B2ia));
    u64 qia = ffma2(ZRa, B2ia, neg2(fmul2(ZIa, B2ra)));
    u64 Pra = fsub2(B1ra, qra);
    u64 Pia = fsub2(B1ia, qia);
    u64 qrb = ffma2(ZRb, B2rb, fmul2(ZIb, B2ib));
    u64 qib = ffma2(ZRb, B2ib, neg2(fmul2(ZIb, B2rb)));
    u64 Prb = fsub2(B1rb, qrb);
    u64 Pib = fsub2(B1ib, qib);

    // result = P * (cm, -sm)
    u64 FRa = ffma2(Pra, CMa, fmul2(Pia, SMa));
    u64 FIa = ffma2(Pia, CMa, neg2(fmul2(Pra, SMa)));
    u64 FRb = ffma2(Prb, CMb, fmul2(Pib, SMb));
    u64 FIb = ffma2(Pib, CMb, neg2(fmul2(Prb, SMb)));

    float r0, r1, r2, r3, i0, i1, i2, i3;
    upk2(FRa, r0, r1); upk2(FRb, r2, r3);
    upk2(FIa, i0, i1); upk2(FIb, i2, i3);

    *(float4*)(out + base)     = make_float4(r0, r1, r2, r3);  // real block
    *(float4*)(out + B + base) = make_float4(i0, i1, i2, i3);  // imag block
}

extern "C" void kernel_launch(void* const* d_in, const int* in_sizes, int n_in,
                              void* d_out, int out_size) {
    const float* th   = (const float*)d_in[0];
    const float* phis = (const float*)d_in[1];
    float* out = (float*)d_out;
    int B = in_sizes[0];

    qsp_coeff_kernel<<<1, NPHI>>>(phis);

    // Stage coefficients into the constant bank (capturable D2D copy).
    void *dst = nullptr, *src = nullptr;
    cudaGetSymbolAddress(&dst, c_coef);
    cudaGetSymbolAddress(&src, g_coefDup);
    cudaMemcpyAsync(dst, src, 2 * NPHI * sizeof(u64), cudaMemcpyDeviceToDevice);

    int nthreads = (B + 3) / 4;                 // 4 thetas per thread
    int blocks = (nthreads + 255) / 256;
    qsp_main_kernel<<<blocks, 256>>>(th, out, B);
}

// round 12
// speedup vs baseline: 1.4668x; 1.4668x over previous
#include <cuda_runtime.h>

#define NPHI 128
#define DEG  127

typedef unsigned long long u64;

// Coefficients C_j of a(w) = w^{-127} * sum_j C_j * (w^2)^j  (complex, 128 entries)
__device__ float2 g_coefA[NPHI];

// ---------------------------------------------------------------------------
// Kernel 1: build the 128 complex coefficients from the phis (one block).
// Pointwise-unitary recurrence => coefficient l2-norm preserved => stable fp32.
// TWO recurrence steps per __syncthreads (barrier-latency bound: 4 warps,
// 127 serial steps). Arrays padded by 2 zeros at the front; A_j lives at
// index j+2. Thread j computes the k and k+1 updates for position j locally
// from the window {j-2, j-1, j}.
// ---------------------------------------------------------------------------
__global__ void qsp_coeff_kernel(const float* __restrict__ phis) {
    __shared__ float er[NPHI], ei[NPHI];
    __shared__ float Ar[2][NPHI + 2], Ai[2][NPHI + 2];
    __shared__ float Br[2][NPHI + 2], Bi[2][NPHI + 2];
    int j = threadIdx.x;  // 0..127

    float s, c;
    sincosf(phis[j], &s, &c);
    er[j] = c; ei[j] = s;

    // zero both buffers (incl. 2-entry front padding, never written again)
    Ar[0][j + 2] = 0.f; Ai[0][j + 2] = 0.f;
    Br[0][j + 2] = 0.f; Bi[0][j + 2] = 0.f;
    Ar[1][j + 2] = 0.f; Ai[1][j + 2] = 0.f;
    Br[1][j + 2] = 0.f; Bi[1][j + 2] = 0.f;
    if (j < 2) {
        Ar[0][j] = Ai[0][j] = Br[0][j] = Bi[0][j] = 0.f;
        Ar[1][j] = Ai[1][j] = Br[1][j] = Bi[1][j] = 0.f;
    }
    __syncthreads();
    if (j == 0) { Ar[0][2] = er[0]; Ai[0][2] = ei[0]; }  // A_0 = e^{i phi_0}
    __syncthreads();

    // Single step k=1 (127 steps total = 1 single + 63 doubles)
    int p = 0;
    {
        int q = 1;
        float am1r = Ar[p][j + 1], am1i = Ai[p][j + 1];  // A[j-1]
        float a0r  = Ar[p][j + 2], a0i  = Ai[p][j + 2];  // A[j]
        float bm1r = Br[p][j + 1], bm1i = Bi[p][j + 1];
        float b0r  = Br[p][j + 2], b0i  = Bi[p][j + 2];

        float tAr = 0.5f * (am1r + a0r + bm1r - b0r);
        float tAi = 0.5f * (am1i + a0i + bm1i - b0i);
        float tBr = 0.5f * (am1r - a0r + bm1r + b0r);
        float tBi = 0.5f * (am1i - a0i + bm1i + b0i);

        float ekr = er[1], eki = ei[1];
        Ar[q][j + 2] = ekr * tAr - eki * tAi;
        Ai[q][j + 2] = ekr * tAi + eki * tAr;
        Br[q][j + 2] = ekr * tBr + eki * tBi;
        Bi[q][j + 2] = ekr * tBi - eki * tBr;
        p = q;
        __syncthreads();
    }

    // 63 double steps: k = 2,4,...,126 (pairs k, k+1)
    for (int k = 2; k <= DEG - 1; k += 2) {
        int q = p ^ 1;
        float a2r = Ar[p][j],     a2i = Ai[p][j];      // A[j-2]
        float a1r = Ar[p][j + 1], a1i = Ai[p][j + 1];  // A[j-1]
        float a0r = Ar[p][j + 2], a0i = Ai[p][j + 2];  // A[j]
        float b2r = Br[p][j],     b2i = Bi[p][j];
        float b1r = Br[p][j + 1], b1i = Bi[p][j + 1];
        float b0r = Br[p][j + 2], b0i = Bi[p][j + 2];

        float ekr = er[k], eki = ei[k];

        // step k at position j
        float tA0r = 0.5f * (a1r + a0r + b1r - b0r);
        float tA0i = 0.5f * (a1i + a0i + b1i - b0i);
        float tB0r = 0.5f * (a1r - a0r + b1r + b0r);
        float tB0i = 0.5f * (a1i - a0i + b1i + b0i);
        float Apjr = ekr * tA0r - eki * tA0i;
        float Apji = ekr * tA0i + eki * tA0r;
        float Bpjr = ekr * tB0r + eki * tB0i;
        float Bpji = ekr * tB0i - eki * tB0r;

        // step k at position j-1
        float tA1r = 0.5f * (a2r + a1r + b2r - b1r);
        float tA1i = 0.5f * (a2i + a1i + b2i - b1i);
        float tB1r = 0.5f * (a2r - a1r + b2r + b1r);
        float tB1i = 0.5f * (a2i - a1i + b2i + b1i);
        float Apmr = ekr * tA1r - eki * tA1i;
        float Apmi = ekr * tA1i + eki * tA1r;
        float Bpmr = ekr * tB1r + eki * tB1i;
        float Bpmi = ekr * tB1i - eki * tB1r;

        // step k+1 at position j
        float e1r = er[k + 1], e1i = ei[k + 1];
        float uAr = 0.5f * (Apmr + Apjr + Bpmr - Bpjr);
        float uAi = 0.5f * (Apmi + Apji + Bpmi - Bpji);
        float uBr = 0.5f * (Apmr - Apjr + Bpmr + Bpjr);
        float uBi = 0.5f * (Apmi - Apji + Bpmi + Bpji);

        Ar[q][j + 2] = e1r * uAr - e1i * uAi;
        Ai[q][j + 2] = e1r * uAi + e1i * uAr;
        Br[q][j + 2] = e1r * uBr + e1i * uBi;
        Bi[q][j + 2] = e1r * uBi - e1i * uBr;

        p = q;
        __syncthreads();
    }

    g_coefA[j] = make_float2(Ar[p][j + 2], Ai[p][j + 2]);
}

// ---------------------------------------------------------------------------
// Packed f32x2 helpers
// ---------------------------------------------------------------------------
__device__ __forceinline__ u64 pk2(float lo, float hi) {
    u64 r; asm("mov.b64 %0,{%1,%2};" : "=l"(r) : "f"(lo), "f"(hi)); return r;
}
__device__ __forceinline__ void upk2(u64 v, float& lo, float& hi) {
    asm("mov.b64 {%0,%1},%2;" : "=f"(lo), "=f"(hi) : "l"(v));
}
__device__ __forceinline__ u64 ffma2(u64 a, u64 b, u64 c) {
    u64 d; asm("fma.rn.f32x2 %0,%1,%2,%3;" : "=l"(d) : "l"(a), "l"(b), "l"(c)); return d;
}
__device__ __forceinline__ u64 fmul2(u64 a, u64 b) {
    u64 d; asm("mul.rn.f32x2 %0,%1,%2;" : "=l"(d) : "l"(a), "l"(b)); return d;
}
__device__ __forceinline__ u64 fsub2(u64 a, u64 b) {
    u64 d; asm("sub.rn.f32x2 %0,%1,%2;" : "=l"(d) : "l"(a), "l"(b)); return d;
}
__device__ __forceinline__ u64 neg2(u64 a) {
    return a ^ 0x8000000080000000ULL;  // flip both fp32 sign bits
}
// One LDS.128 -> two u64 (coefficient pair)
__device__ __forceinline__ void lds_v2b64(u64& a, u64& b, unsigned saddr) {
    asm volatile("ld.shared.v2.b64 {%0,%1},[%2];" : "=l"(a), "=l"(b) : "r"(saddr));
}

// ---------------------------------------------------------------------------
// Kernel 2: 4 thetas/thread = two packed (f32x2) Goertzel chains sharing one
// broadcast LDS.128 per coefficient.
//   P(z) = sum_j C_j z^j,  z = e^{2i theta}:
//     b_k = C_k + 2*Re(z)*b_{k+1} - b_{k+2}
//     P   = b_0 - conj(z)*b_1
//   result = P * e^{-127 i theta}   (direct __sincosf(127*theta))
// ---------------------------------------------------------------------------
__global__ void __launch_bounds__(256) qsp_main_kernel(const float* __restrict__ th,
                                                       float* __restrict__ out, int B) {
    __shared__ __align__(16) u64 sC[2 * NPHI];  // interleaved (CR, CI), lanes duplicated
    int t = threadIdx.x;
    if (t < NPHI) {
        float2 cc = g_coefA[t];
        sC[2 * t]     = pk2(cc.x, cc.x);
        sC[2 * t + 1] = pk2(cc.y, cc.y);
    }
    __syncthreads();

    unsigned sbase = (unsigned)__cvta_generic_to_shared(sC);

    int base = (blockIdx.x * blockDim.x + t) * 4;
    if (base >= B) return;

    float4 T = *(const float4*)(th + base);

    float zr0, zi0, zr1, zi1, zr2, zi2, zr3, zi3;   // z = e^{2i theta}
    float cm0, sm0, cm1, sm1, cm2, sm2, cm3, sm3;   // e^{i*127 theta}
    __sincosf(2.f * T.x, &zi0, &zr0);
    __sincosf(2.f * T.y, &zi1, &zr1);
    __sincosf(2.f * T.z, &zi2, &zr2);
    __sincosf(2.f * T.w, &zi3, &zr3);
    __sincosf(127.f * T.x, &sm0, &cm0);
    __sincosf(127.f * T.y, &sm1, &cm1);
    __sincosf(127.f * T.z, &sm2, &cm2);
    __sincosf(127.f * T.w, &sm3, &cm3);

    u64 ZRa = pk2(zr0, zr1), ZIa = pk2(zi0, zi1);
    u64 ZRb = pk2(zr2, zr3), ZIb = pk2(zi2, zi3);
    u64 Ya  = pk2(2.f * zr0, 2.f * zr1);           // 2*Re(z)
    u64 Yb  = pk2(2.f * zr2, 2.f * zr3);
    u64 CMa = pk2(cm0, cm1), SMa = pk2(sm0, sm1);
    u64 CMb = pk2(cm2, cm3), SMb = pk2(sm2, sm3);

    // Goertzel init: b_127 = C_127, b_128 = 0
    u64 B1ra, B1ia;
    lds_v2b64(B1ra, B1ia, sbase + 16u * DEG);
    u64 B1rb = B1ra, B1ib = B1ia;
    u64 B2ra = 0, B2ia = 0, B2rb = 0, B2ib = 0;

#pragma unroll 8
    for (int k = DEG - 1; k >= 0; k--) {
        u64 CR, CI;
        lds_v2b64(CR, CI, sbase + 16u * (unsigned)k);
        // chain a
        u64 tra = fsub2(CR, B2ra);
        u64 tia = fsub2(CI, B2ia);
        u64 nra = ffma2(Ya, B1ra, tra);
        u64 nia = ffma2(Ya, B1ia, tia);
        B2ra = B1ra; B2ia = B1ia; B1ra = nra; B1ia = nia;
        // chain b
        u64 trb = fsub2(CR, B2rb);
        u64 tib = fsub2(CI, B2ib);
        u64 nrb = ffma2(Yb, B1rb, trb);
        u64 nib = ffma2(Yb, B1ib, tib);
        B2rb = B1rb; B2ib = B1ib; B1rb = nrb; B1ib = nib;
    }
    // B1 = b_0, B2 = b_1.  P = b_0 - conj(z)*b_1
    u64 qra = ffma2(ZRa, B2ra, fmul2(ZIa, B2ia));
    u64 qia = ffma2(ZRa, B2ia, neg2(fmul2(ZIa, B2ra)));
    u64 Pra = fsub2(B1ra, qra);
    u64 Pia = fsub2(B1ia, qia);
    u64 qrb = ffma2(ZRb, B2rb, fmul2(ZIb, B2ib));
    u64 qib = ffma2(ZRb, B2ib, neg2(fmul2(ZIb, B2rb)));
    u64 Prb = fsub2(B1rb, qrb);
    u64 Pib = fsub2(B1ib, qib);

    // result = P * (cm, -sm)
    u64 FRa = ffma2(Pra, CMa, fmul2(Pia, SMa));
    u64 FIa = ffma2(Pia, CMa, neg2(fmul2(Pra, SMa)));
    u64 FRb = ffma2(Prb, CMb, fmul2(Pib, SMb));
    u64 FIb = ffma2(Pib, CMb, neg2(fmul2(Prb, SMb)));

    float r0, r1, r2, r3, i0, i1, i2, i3;
    upk2(FRa, r0, r1); upk2(FRb, r2, r3);
    upk2(FIa, i0, i1); upk2(FIb, i2, i3);

    *(float4*)(out + base)     = make_float4(r0, r1, r2, r3);  // real block
    *(float4*)(out + B + base) = make_float4(i0, i1, i2, i3);  // imag block
}

extern "C" void kernel_launch(void* const* d_in, const int* in_sizes, int n_in,
                              void* d_out, int out_size) {
    const float* th   = (const float*)d_in[0];
    const float* phis = (const float*)d_in[1];
    float* out = (float*)d_out;
    int B = in_sizes[0];

    qsp_coeff_kernel<<<1, NPHI>>>(phis);

    int nthreads = (B + 3) / 4;                 // 4 thetas per thread
    int blocks = (nthreads + 255) / 256;
    qsp_main_kernel<<<blocks, 256>>>(th, out, B);
}

// round 13
// speedup vs baseline: 1.5171x; 1.0343x over previous
#include <cuda_runtime.h>

#define NPHI 128
#define DEG  127

typedef unsigned long long u64;

// Coefficients C_j of a(w) = w^{-127} * sum_j C_j * (w^2)^j  (complex, 128 entries)
__device__ float2 g_coefA[NPHI];

// ---------------------------------------------------------------------------
// One recurrence step applied at a single position.
// v = (Ar, Ai, Br, Bi); vm1 = same arrays at position-1; e = 0.5*e^{i phi_k}.
//   A' = e     * 0.5*((A[-1] + A) + (B[-1] - B))
//   B' = conj(e)*0.5*((A[-1] - A) + (B[-1] + B))
// (0.5 folded into e)
// ---------------------------------------------------------------------------
__device__ __forceinline__ float4 cstep(float4 vm1, float4 v0, float2 e) {
    float tAr = vm1.x + v0.x + vm1.z - v0.z;
    float tAi = vm1.y + v0.y + vm1.w - v0.w;
    float tBr = vm1.x - v0.x + vm1.z + v0.z;
    float tBi = vm1.y - v0.y + vm1.w + v0.w;
    float4 o;
    o.x = e.x * tAr - e.y * tAi;
    o.y = e.x * tAi + e.y * tAr;
    o.z = e.x * tBr + e.y * tBi;
    o.w = e.x * tBi - e.y * tBr;
    return o;
}

// ---------------------------------------------------------------------------
// Kernel 1: build the 128 complex coefficients from the phis (one block).
// Pointwise-unitary recurrence => l2-norm preserved => stable fp32.
// FOUR recurrence steps per __syncthreads: thread j reads positions j-4..j
// (float4-packed state, one LDS.128 each) and computes the 4-step wavefront
// locally (10 cstep calls), writing only position j. 127 = 3 + 31*4 steps
// -> 34 barriers total (vs 65 before).
// Ends with threadfence + griddepcontrol.launch_dependents so the PDL-launched
// main kernel can start its prologue early and wait only before reading coeffs.
// ---------------------------------------------------------------------------
__global__ void qsp_coeff_kernel(const float* __restrict__ phis) {
    __shared__ float2 e2[NPHI];          // 0.5 * e^{i phi_k}
    __shared__ float4 V[2][NPHI + 4];    // position j lives at index j+4
    int j = threadIdx.x;  // 0..127

    float s, c;
    sincosf(phis[j], &s, &c);
    e2[j] = make_float2(0.5f * c, 0.5f * s);

    V[0][j + 4] = make_float4(0.f, 0.f, 0.f, 0.f);
    V[1][j + 4] = make_float4(0.f, 0.f, 0.f, 0.f);
    if (j < 4) {
        V[0][j] = make_float4(0.f, 0.f, 0.f, 0.f);
        V[1][j] = make_float4(0.f, 0.f, 0.f, 0.f);
    }
    __syncthreads();
    if (j == 0) V[0][4] = make_float4(c, s, 0.f, 0.f);  // A_0 = e^{i phi_0} (unhalved)
    __syncthreads();

    int p = 0;
    // steps k = 1..3 fused
    {
        float4 w0 = V[p][j + 1], w1 = V[p][j + 2], w2 = V[p][j + 3], w3 = V[p][j + 4];
        float2 e;
        e = e2[1]; w3 = cstep(w2, w3, e); w2 = cstep(w1, w2, e); w1 = cstep(w0, w1, e);
        e = e2[2]; w3 = cstep(w2, w3, e); w2 = cstep(w1, w2, e);
        e = e2[3]; w3 = cstep(w2, w3, e);
        V[1][j + 4] = w3;
        p = 1;
        __syncthreads();
    }
    // steps k = 4..127: 31 supersteps of 4
    for (int k = 4; k <= 124; k += 4) {
        int q = p ^ 1;
        float4 w0 = V[p][j],     w1 = V[p][j + 1], w2 = V[p][j + 2];
        float4 w3 = V[p][j + 3], w4 = V[p][j + 4];
        float2 e;
        e = e2[k];     w4 = cstep(w3, w4, e); w3 = cstep(w2, w3, e);
                       w2 = cstep(w1, w2, e); w1 = cstep(w0, w1, e);
        e = e2[k + 1]; w4 = cstep(w3, w4, e); w3 = cstep(w2, w3, e);
                       w2 = cstep(w1, w2, e);
        e = e2[k + 2]; w4 = cstep(w3, w4, e); w3 = cstep(w2, w3, e);
        e = e2[k + 3]; w4 = cstep(w3, w4, e);
        V[q][j + 4] = w4;
        p = q;
        __syncthreads();
    }

    float4 r = V[p][j + 4];
    g_coefA[j] = make_float2(r.x, r.y);
    __threadfence();
    asm volatile("griddepcontrol.launch_dependents;");
}

// ---------------------------------------------------------------------------
// Packed f32x2 helpers
// ---------------------------------------------------------------------------
__device__ __forceinline__ u64 pk2(float lo, float hi) {
    u64 r; asm("mov.b64 %0,{%1,%2};" : "=l"(r) : "f"(lo), "f"(hi)); return r;
}
__device__ __forceinline__ void upk2(u64 v, float& lo, float& hi) {
    asm("mov.b64 {%0,%1},%2;" : "=f"(lo), "=f"(hi) : "l"(v));
}
__device__ __forceinline__ u64 ffma2(u64 a, u64 b, u64 c) {
    u64 d; asm("fma.rn.f32x2 %0,%1,%2,%3;" : "=l"(d) : "l"(a), "l"(b), "l"(c)); return d;
}
__device__ __forceinline__ u64 fmul2(u64 a, u64 b) {
    u64 d; asm("mul.rn.f32x2 %0,%1,%2;" : "=l"(d) : "l"(a), "l"(b)); return d;
}
__device__ __forceinline__ u64 fsub2(u64 a, u64 b) {
    u64 d; asm("sub.rn.f32x2 %0,%1,%2;" : "=l"(d) : "l"(a), "l"(b)); return d;
}
__device__ __forceinline__ u64 neg2(u64 a) {
    return a ^ 0x8000000080000000ULL;  // flip both fp32 sign bits
}
// One LDS.128 -> two u64 (coefficient pair)
__device__ __forceinline__ void lds_v2b64(u64& a, u64& b, unsigned saddr) {
    asm volatile("ld.shared.v2.b64 {%0,%1},[%2];" : "=l"(a), "=l"(b) : "r"(saddr));
}

// ---------------------------------------------------------------------------
// Kernel 2: 4 thetas/thread = two packed (f32x2) Goertzel chains sharing one
// broadcast LDS.128 per coefficient.
//   P(z) = sum_j C_j z^j,  z = e^{2i theta}:
//     b_k = C_k + 2*Re(z)*b_{k+1} - b_{k+2}
//     P   = b_0 - conj(z)*b_1
//   result = P * e^{-127 i theta}   (direct __sincosf(127*theta))
// Prologue (theta loads + MUFU sincos) runs BEFORE griddepcontrol.wait so it
// overlaps the PDL-predecessor coeff kernel.
// ---------------------------------------------------------------------------
__global__ void __launch_bounds__(256) qsp_main_kernel(const float* __restrict__ th,
                                                       float* __restrict__ out, int B) {
    int t = threadIdx.x;
    int base = (blockIdx.x * blockDim.x + t) * 4;
    bool valid = (base < B);
    int lbase = valid ? base : 0;

    float4 T = *(const float4*)(th + lbase);

    float zr0, zi0, zr1, zi1, zr2, zi2, zr3, zi3;   // z = e^{2i theta}
    float cm0, sm0, cm1, sm1, cm2, sm2, cm3, sm3;   // e^{i*127 theta}
    __sincosf(2.f * T.x, &zi0, &zr0);
    __sincosf(2.f * T.y, &zi1, &zr1);
    __sincosf(2.f * T.z, &zi2, &zr2);
    __sincosf(2.f * T.w, &zi3, &zr3);
    __sincosf(127.f * T.x, &sm0, &cm0);
    __sincosf(127.f * T.y, &sm1, &cm1);
    __sincosf(127.f * T.z, &sm2, &cm2);
    __sincosf(127.f * T.w, &sm3, &cm3);

    u64 ZRa = pk2(zr0, zr1), ZIa = pk2(zi0, zi1);
    u64 ZRb = pk2(zr2, zr3), ZIb = pk2(zi2, zi3);
    u64 Ya  = pk2(2.f * zr0, 2.f * zr1);           // 2*Re(z)
    u64 Yb  = pk2(2.f * zr2, 2.f * zr3);
    u64 CMa = pk2(cm0, cm1), SMa = pk2(sm0, sm1);
    u64 CMb = pk2(cm2, cm3), SMb = pk2(sm2, sm3);

    // Wait for the PDL predecessor's coefficients, then stage into smem.
    asm volatile("griddepcontrol.wait;" ::: "memory");

    __shared__ __align__(16) u64 sC[2 * NPHI];  // interleaved (CR, CI), lanes duplicated
    if (t < NPHI) {
        float2 cc = g_coefA[t];
        sC[2 * t]     = pk2(cc.x, cc.x);
        sC[2 * t + 1] = pk2(cc.y, cc.y);
    }
    __syncthreads();

    unsigned sbase = (unsigned)__cvta_generic_to_shared(sC);

    // Goertzel init: b_127 = C_127, b_128 = 0
    u64 B1ra, B1ia;
    lds_v2b64(B1ra, B1ia, sbase + 16u * DEG);
    u64 B1rb = B1ra, B1ib = B1ia;
    u64 B2ra = 0, B2ia = 0, B2rb = 0, B2ib = 0;

#pragma unroll 8
    for (int k = DEG - 1; k >= 0; k--) {
        u64 CR, CI;
        lds_v2b64(CR, CI, sbase + 16u * (unsigned)k);
        // chain a
        u64 tra = fsub2(CR, B2ra);
        u64 tia = fsub2(CI, B2ia);
        u64 nra = ffma2(Ya, B1ra, tra);
        u64 nia = ffma2(Ya, B1ia, tia);
        B2ra = B1ra; B2ia = B1ia; B1ra = nra; B1ia = nia;
        // chain b
        u64 trb = fsub2(CR, B2rb);
        u64 tib = fsub2(CI, B2ib);
        u64 nrb = ffma2(Yb, B1rb, trb);
        u64 nib = ffma2(Yb, B1ib, tib);
        B2rb = B1rb; B2ib = B1ib; B1rb = nrb; B1ib = nib;
    }
    // B1 = b_0, B2 = b_1.  P = b_0 - conj(z)*b_1
    u64 qra = ffma2(ZRa, B2ra, fmul2(ZIa, B2ia));
    u64 qia = ffma2(ZRa, B2ia, neg2(fmul2(ZIa, B2ra)));
    u64 Pra = fsub2(B1ra, qra);
    u64 Pia = fsub2(B1ia, qia);
    u64 qrb = ffma2(ZRb, B2rb, fmul2(ZIb, B2ib));
    u64 qib = ffma2(ZRb, B2ib, neg2(fmul2(ZIb, B2rb)));
    u64 Prb = fsub2(B1rb, qrb);
    u64 Pib = fsub2(B1ib, qib);

    // result = P * (cm, -sm)
    u64 FRa = ffma2(Pra, CMa, fmul2(Pia, SMa));
    u64 FIa = ffma2(Pia, CMa, neg2(fmul2(Pra, SMa)));
    u64 FRb = ffma2(Prb, CMb, fmul2(Pib, SMb));
    u64 FIb = ffma2(Pib, CMb, neg2(fmul2(Prb, SMb)));

    if (!valid) return;

    float r0, r1, r2, r3, i0, i1, i2, i3;
    upk2(FRa, r0, r1); upk2(FRb, r2, r3);
    upk2(FIa, i0, i1); upk2(FIb, i2, i3);

    *(float4*)(out + base)     = make_float4(r0, r1, r2, r3);  // real block
    *(float4*)(out + B + base) = make_float4(i0, i1, i2, i3);  // imag block
}

extern "C" void kernel_launch(void* const* d_in, const int* in_sizes, int n_in,
                              void* d_out, int out_size) {
    const float* th   = (const float*)d_in[0];
    const float* phis = (const float*)d_in[1];
    float* out = (float*)d_out;
    int B = in_sizes[0];

    qsp_coeff_kernel<<<1, NPHI>>>(phis);

    int nthreads = (B + 3) / 4;                 // 4 thetas per thread
    int blocks = (nthreads + 255) / 256;

    // PDL launch: main may begin (and run its sincos prologue) while the coeff
    // kernel is still finishing; griddepcontrol.wait gates the coefficient read.
    cudaLaunchConfig_t cfg = {};
    cfg.gridDim  = dim3((unsigned)blocks, 1, 1);
    cfg.blockDim = dim3(256, 1, 1);
    cudaLaunchAttribute attr[1];
    attr[0].id = cudaLaunchAttributeProgrammaticStreamSerialization;
    attr[0].val.programmaticStreamSerializationAllowed = 1;
    cfg.attrs = attr;
    cfg.numAttrs = 1;
    cudaLaunchKernelEx(&cfg, qsp_main_kernel, th, out, B);
}